// round 3
// baseline (speedup 1.0000x reference)
#include <cuda_runtime.h>
#include <cstdint>

// ---------------------------------------------------------------------------
// QINCo inference step encoder, factorized:
//   g(k)  = (codebook@W_in + b_in) @ Wc
//   t(bf) = xhat@Wx + b_cat
//   u1 = A1g[k] + A1t[bf];            r1 = relu(u1)
//   u2 = A2g[k] + A2t[bf] + r1@M12;   r2 = relu(u2)     (M12 = W2[0]@W1[1])
//   cw = Og[k] + Ot[bf] + r1@M1o + r2@M2o               (M1o=W2[0]@W_out, M2o=W2[1]@W_out)
//   dist(b,f,k) = || Og[k] + (Ot[bf]-x_b) + corr ||^2 ; argmin per b; recompute winner row.
//
// Output buffer: 33152 float32 = [xhat_next: 32768 f32][codes_new: 384 f32 values]
// Codes input: int32 (256 values) — JAX default config downcasts int64.
// ---------------------------------------------------------------------------

#define Bb   128
#define Ff   8
#define Kk   256
#define Dd   256
#define Hh   256
#define HFF  512

// -------------------- scratch (device globals; no allocs) -------------------
__device__ float g_h0 [Kk*Hh];
__device__ float g_g  [Kk*Hh];
__device__ float g_t  [Bb*Ff*Hh];
__device__ float g_A1g[Kk*HFF];
__device__ float g_A2g[Kk*HFF];
__device__ float g_A1t[Bb*Ff*HFF];
__device__ float g_A2t[Bb*Ff*HFF];
__device__ float g_Og [Kk*Dd];
__device__ float g_Ot [Bb*Ff*Dd];
__device__ float g_M12[HFF*HFF];
__device__ float g_M1o[HFF*Dd];
__device__ float g_M2o[HFF*Dd];
__device__ float g_bu2[HFF];
__device__ float g_bo [Dd];
__device__ float g_dists[Bb*Ff*Kk];
__device__ int   g_idx[Bb];

// -------------------- generic small SGEMM: C = A@B (+bias)(+Add) ------------
// BM=BN=64, BK=16, 256 threads, 4x4 per thread. M,N multiples of 64; K of 16.
__global__ __launch_bounds__(256) void sgemm64(
    const float* __restrict__ A, const float* __restrict__ B, float* __restrict__ C,
    int M, int N, int K, const float* __restrict__ bias, const float* __restrict__ add)
{
    __shared__ float As[16][65];
    __shared__ float Bs[16][64];
    const int m0 = blockIdx.y * 64;
    const int n0 = blockIdx.x * 64;
    const int tid = threadIdx.x;
    const int tx = tid & 15, ty = tid >> 4;
    float acc[4][4] = {};

    for (int k0 = 0; k0 < K; k0 += 16) {
        {   // A tile 64x16 (float4 per thread)
            int ra = tid >> 2, ca = (tid & 3) * 4;
            float4 av = *(const float4*)(A + (size_t)(m0 + ra) * K + k0 + ca);
            As[ca+0][ra] = av.x; As[ca+1][ra] = av.y;
            As[ca+2][ra] = av.z; As[ca+3][ra] = av.w;
        }
        {   // B tile 16x64
            int rb = tid >> 4, cb = (tid & 15) * 4;
            *(float4*)&Bs[rb][cb] = *(const float4*)(B + (size_t)(k0 + rb) * N + n0 + cb);
        }
        __syncthreads();
        #pragma unroll
        for (int kk = 0; kk < 16; kk++) {
            float a0 = As[kk][ty*4+0], a1 = As[kk][ty*4+1];
            float a2 = As[kk][ty*4+2], a3 = As[kk][ty*4+3];
            float4 bv = *(float4*)&Bs[kk][tx*4];
            acc[0][0] += a0*bv.x; acc[0][1] += a0*bv.y; acc[0][2] += a0*bv.z; acc[0][3] += a0*bv.w;
            acc[1][0] += a1*bv.x; acc[1][1] += a1*bv.y; acc[1][2] += a1*bv.z; acc[1][3] += a1*bv.w;
            acc[2][0] += a2*bv.x; acc[2][1] += a2*bv.y; acc[2][2] += a2*bv.z; acc[2][3] += a2*bv.w;
            acc[3][0] += a3*bv.x; acc[3][1] += a3*bv.y; acc[3][2] += a3*bv.z; acc[3][3] += a3*bv.w;
        }
        __syncthreads();
    }
    #pragma unroll
    for (int i = 0; i < 4; i++) {
        int m = m0 + ty*4 + i;
        #pragma unroll
        for (int j = 0; j < 4; j++) {
            int n = n0 + tx*4 + j;
            float v = acc[i][j];
            if (bias) v += bias[n];
            if (add)  v += add[(size_t)m * N + n];
            C[(size_t)m * N + n] = v;
        }
    }
}

// out[j] = base[j] + sum_i (v1[i] + v2?[i]) * Mat[i*N + j]
__global__ void vecmat_bias(float* __restrict__ out, const float* __restrict__ base,
                            const float* __restrict__ v1, const float* __restrict__ v2,
                            const float* __restrict__ Mat, int K, int N)
{
    int j = blockIdx.x * blockDim.x + threadIdx.x;
    if (j >= N) return;
    float s = base[j];
    for (int i = 0; i < K; i++) {
        float v = v1[i];
        if (v2) v += v2[i];
        s += v * Mat[(size_t)i * N + j];
    }
    out[j] = s;
}

// -------------------- main distance kernel ----------------------------------
// One CTA per (b,f). 256 threads. k processed in tiles of 32 rows.
// Register tile: C panel 32(M) x 128(N); threads laid out tm(0..7) x tn(0..31),
// 4x4 per thread. A-side lives in smem (R1 / R2), B streamed via Bt.
__device__ __forceinline__ void gemm_tile16(
    float* __restrict__ acc, const float* __restrict__ Asm, int lda,
    const float* __restrict__ Bg, int ldb, int kTot,
    float (*Bt)[128], int tid, int tm, int tn)
{
    const float* a0p = Asm + (tm*4+0)*lda;
    const float* a1p = Asm + (tm*4+1)*lda;
    const float* a2p = Asm + (tm*4+2)*lda;
    const float* a3p = Asm + (tm*4+3)*lda;
    const int rw = tid >> 5;
    const int c4 = (tid & 31) * 4;
    for (int kc = 0; kc < kTot; kc += 32) {
        __syncthreads();   // protect Bt from previous consumers
        #pragma unroll
        for (int i = 0; i < 4; i++) {
            int r = rw + i * 8;
            *(float4*)&Bt[r][c4] = *(const float4*)(Bg + (size_t)(kc + r) * ldb + c4);
        }
        __syncthreads();
        #pragma unroll
        for (int kk4 = 0; kk4 < 32; kk4 += 4) {
            float a0[4], a1[4], a2[4], a3[4];
            *(float4*)a0 = *(const float4*)(a0p + kc + kk4);
            *(float4*)a1 = *(const float4*)(a1p + kc + kk4);
            *(float4*)a2 = *(const float4*)(a2p + kc + kk4);
            *(float4*)a3 = *(const float4*)(a3p + kc + kk4);
            #pragma unroll
            for (int q = 0; q < 4; q++) {
                float4 bv = *(float4*)&Bt[kk4 + q][tn*4];
                acc[ 0] += a0[q]*bv.x; acc[ 1] += a0[q]*bv.y; acc[ 2] += a0[q]*bv.z; acc[ 3] += a0[q]*bv.w;
                acc[ 4] += a1[q]*bv.x; acc[ 5] += a1[q]*bv.y; acc[ 6] += a1[q]*bv.z; acc[ 7] += a1[q]*bv.w;
                acc[ 8] += a2[q]*bv.x; acc[ 9] += a2[q]*bv.y; acc[10] += a2[q]*bv.z; acc[11] += a2[q]*bv.w;
                acc[12] += a3[q]*bv.x; acc[13] += a3[q]*bv.y; acc[14] += a3[q]*bv.z; acc[15] += a3[q]*bv.w;
            }
        }
    }
}

#define DIST_SMEM_FLOATS (512 + 512 + 256 + 32*512 + 32*128 + 32*128)

__global__ __launch_bounds__(256) void dist_kernel(const float* __restrict__ x)
{
    extern __shared__ float sm[];
    float* a1t = sm;                //  512
    float* a2t = sm + 512;          //  512
    float* otx = sm + 1024;         //  256
    float* R1f = sm + 1280;         //  32*512
    float (*R1)[512] = (float(*)[512])R1f;
    float (*Bt)[128]  = (float(*)[128])(R1f + 32*512);
    float (*R2)[128]  = (float(*)[128])(R1f + 32*512 + 32*128);

    const int bf = blockIdx.x;
    const int b  = bf >> 3;
    const int f  = bf & 7;
    const int tid = threadIdx.x;
    const int tm = tid >> 5, tn = tid & 31;

    for (int i = tid; i < 512; i += 256) {
        a1t[i] = g_A1t[(size_t)bf*512 + i];
        a2t[i] = g_A2t[(size_t)bf*512 + i];
    }
    if (tid < 256) otx[tid] = g_Ot[(size_t)bf*256 + tid] - x[(size_t)b*256 + tid];

    #pragma unroll 1
    for (int k0 = 0; k0 < 256; k0 += 32) {
        __syncthreads();   // protect R1 from previous iteration's readers
        for (int i = tid; i < 32*512; i += 256) {
            int r = i >> 9, c = i & 511;
            R1[r][c] = fmaxf(g_A1g[(size_t)(k0 + r)*512 + c] + a1t[c], 0.f);
        }
        // (gemm_tile16's leading barrier orders R1 writes before reads)

        float corr0[16] = {}, corr1[16] = {};
        gemm_tile16(corr0, R1f, 512, g_M1o,       256, 512, Bt, tid, tm, tn);
        gemm_tile16(corr1, R1f, 512, g_M1o + 128, 256, 512, Bt, tid, tm, tn);

        #pragma unroll 1
        for (int p = 0; p < 4; p++) {
            float u2[16] = {};
            gemm_tile16(u2, R1f, 512, g_M12 + p*128, 512, 512, Bt, tid, tm, tn);
            __syncthreads();   // previous panel's R2 readers done
            #pragma unroll
            for (int i = 0; i < 4; i++) {
                int r = tm*4 + i;
                float4 gv = *(const float4*)(g_A2g + (size_t)(k0 + r)*512 + p*128 + tn*4);
                float4 tv = *(const float4*)(a2t + p*128 + tn*4);
                R2[r][tn*4+0] = fmaxf(u2[i*4+0] + gv.x + tv.x, 0.f);
                R2[r][tn*4+1] = fmaxf(u2[i*4+1] + gv.y + tv.y, 0.f);
                R2[r][tn*4+2] = fmaxf(u2[i*4+2] + gv.z + tv.z, 0.f);
                R2[r][tn*4+3] = fmaxf(u2[i*4+3] + gv.w + tv.w, 0.f);
            }
            gemm_tile16(corr0, (const float*)R2, 128, g_M2o + (size_t)p*128*256,       256, 128, Bt, tid, tm, tn);
            gemm_tile16(corr1, (const float*)R2, 128, g_M2o + (size_t)p*128*256 + 128, 256, 128, Bt, tid, tm, tn);
        }

        // distances for the 32 rows of this tile
        float part[4] = {};
        #pragma unroll
        for (int i = 0; i < 4; i++) {
            int r = tm*4 + i;
            float4 og0 = *(const float4*)(g_Og + (size_t)(k0 + r)*256 + tn*4);
            float4 og1 = *(const float4*)(g_Og + (size_t)(k0 + r)*256 + 128 + tn*4);
            float4 ox0 = *(const float4*)(otx + tn*4);
            float4 ox1 = *(const float4*)(otx + 128 + tn*4);
            float v;
            v = og0.x + ox0.x + corr0[i*4+0]; part[i] += v*v;
            v = og0.y + ox0.y + corr0[i*4+1]; part[i] += v*v;
            v = og0.z + ox0.z + corr0[i*4+2]; part[i] += v*v;
            v = og0.w + ox0.w + corr0[i*4+3]; part[i] += v*v;
            v = og1.x + ox1.x + corr1[i*4+0]; part[i] += v*v;
            v = og1.y + ox1.y + corr1[i*4+1]; part[i] += v*v;
            v = og1.z + ox1.z + corr1[i*4+2]; part[i] += v*v;
            v = og1.w + ox1.w + corr1[i*4+3]; part[i] += v*v;
        }
        #pragma unroll
        for (int i = 0; i < 4; i++) {
            #pragma unroll
            for (int off = 16; off > 0; off >>= 1)
                part[i] += __shfl_xor_sync(0xffffffffu, part[i], off);
        }
        if (tn == 0) {
            #pragma unroll
            for (int i = 0; i < 4; i++)
                g_dists[(size_t)b*2048 + f*256 + k0 + tm*4 + i] = part[i];
        }
    }
}

// -------------------- argmin per b (first occurrence on ties) ---------------
__global__ __launch_bounds__(256) void argmin_kernel()
{
    __shared__ float sv[256];
    __shared__ int   si[256];
    int b = blockIdx.x, tid = threadIdx.x;
    float best = 3.4e38f; int bi = 1 << 30;
    for (int i = tid; i < 2048; i += 256) {
        float v = g_dists[(size_t)b*2048 + i];
        if (v < best || (v == best && i < bi)) { best = v; bi = i; }
    }
    sv[tid] = best; si[tid] = bi;
    __syncthreads();
    for (int s = 128; s > 0; s >>= 1) {
        if (tid < s) {
            if (sv[tid+s] < sv[tid] || (sv[tid+s] == sv[tid] && si[tid+s] < si[tid])) {
                sv[tid] = sv[tid+s]; si[tid] = si[tid+s];
            }
        }
        __syncthreads();
    }
    if (tid == 0) g_idx[b] = si[0];
}

// -------------------- winner recompute + output -----------------------------
__global__ __launch_bounds__(512) void final_kernel(float* __restrict__ out)
{
    __shared__ float r1[512], r2[512];
    __shared__ int sIdx;
    int b = blockIdx.x, tid = threadIdx.x;
    if (tid == 0) sIdx = g_idx[b];
    __syncthreads();
    int idx = sIdx;
    int f = idx >> 8, k = idx & 255;
    int bf = b*8 + f;

    r1[tid] = fmaxf(g_A1g[(size_t)k*512 + tid] + g_A1t[(size_t)bf*512 + tid], 0.f);
    __syncthreads();
    {
        float s = g_A2g[(size_t)k*512 + tid] + g_A2t[(size_t)bf*512 + tid];
        for (int i = 0; i < 512; i++) s += r1[i] * g_M12[(size_t)i*512 + tid];
        r2[tid] = fmaxf(s, 0.f);
    }
    __syncthreads();
    if (tid < 256) {
        float s = g_Og[(size_t)k*256 + tid] + g_Ot[(size_t)bf*256 + tid];
        for (int i = 0; i < 512; i++)
            s += r1[i] * g_M1o[(size_t)i*256 + tid] + r2[i] * g_M2o[(size_t)i*256 + tid];
        out[b*256 + tid] = s;
    }
}

// codes_new as FLOAT32 VALUES in floats [32768 : 33152]:
//   [codes_MBF (256 int32 -> float), idx (128 -> float)]
// Evidence: R1 err 2.155e15 == float compare of float(int64-pair OOB reads)
// (codes input is int32, 1024 bytes; reading as int64 ran past the buffer);
// R2 err ~1.0 == float32 read of raw int64 bytes (denormals ~ 0).
__global__ void codes_kernel(const int* __restrict__ codes, float* __restrict__ out)
{
    int t = threadIdx.x;
    float* oc = out + Bb * Dd;  // float offset 32768
    if (t < 256)      oc[t] = (float)codes[t];
    else if (t < 384) oc[t] = (float)g_idx[t - 256];
}

// -------------------- launch ------------------------------------------------
extern "C" void kernel_launch(void* const* d_in, const int* in_sizes, int n_in,
                              void* d_out, int out_size)
{
    const float* x        = (const float*)d_in[0];
    const float* xhat     = (const float*)d_in[1];
    const int*   codes    = (const int*)d_in[2];   // int32!
    const float* codebook = (const float*)d_in[3];
    const float* W_in     = (const float*)d_in[4];
    const float* b_in     = (const float*)d_in[5];
    const float* W_cat    = (const float*)d_in[6];
    const float* b_cat    = (const float*)d_in[7];
    const float* W1       = (const float*)d_in[8];
    const float* b1       = (const float*)d_in[9];
    const float* W2       = (const float*)d_in[10];
    const float* b2       = (const float*)d_in[11];
    const float* W_out    = (const float*)d_in[12];
    const float* b_out    = (const float*)d_in[13];
    float* out = (float*)d_out;

    float *p_h0, *p_g, *p_t, *p_A1g, *p_A2g, *p_A1t, *p_A2t, *p_Og, *p_Ot;
    float *p_M12, *p_M1o, *p_M2o, *p_bu2, *p_bo;
    cudaGetSymbolAddress((void**)&p_h0,  g_h0);
    cudaGetSymbolAddress((void**)&p_g,   g_g);
    cudaGetSymbolAddress((void**)&p_t,   g_t);
    cudaGetSymbolAddress((void**)&p_A1g, g_A1g);
    cudaGetSymbolAddress((void**)&p_A2g, g_A2g);
    cudaGetSymbolAddress((void**)&p_A1t, g_A1t);
    cudaGetSymbolAddress((void**)&p_A2t, g_A2t);
    cudaGetSymbolAddress((void**)&p_Og,  g_Og);
    cudaGetSymbolAddress((void**)&p_Ot,  g_Ot);
    cudaGetSymbolAddress((void**)&p_M12, g_M12);
    cudaGetSymbolAddress((void**)&p_M1o, g_M1o);
    cudaGetSymbolAddress((void**)&p_M2o, g_M2o);
    cudaGetSymbolAddress((void**)&p_bu2, g_bu2);
    cudaGetSymbolAddress((void**)&p_bo,  g_bo);

    const float* W1_0 = W1;                const float* W1_1 = W1 + 256*512;
    const float* W2_0 = W2;                const float* W2_1 = W2 + 512*256;
    const float* Wc   = W_cat;             const float* Wx   = W_cat + 256*256;
    const float* b1_1 = b1 + 512;
    const float* b2_0 = b2;                const float* b2_1 = b2 + 256;

    // bias folds: bu2 = b1[1] + b2[0]@W1[1] ; bo = b_out + (b2[0]+b2[1])@W_out
    vecmat_bias<<<2, 256>>>(p_bu2, b1_1, b2_0, nullptr, W1_1, 256, 512);
    vecmat_bias<<<1, 256>>>(p_bo,  b_out, b2_0, b2_1,   W_out, 256, 256);

    // precompute GEMMs
    sgemm64<<<dim3(4, 4),  256>>>(codebook, W_in,  p_h0,  256, 256, 256, b_in,  nullptr);
    sgemm64<<<dim3(4, 4),  256>>>(p_h0,     Wc,    p_g,   256, 256, 256, nullptr, nullptr);
    sgemm64<<<dim3(4, 16), 256>>>(xhat,     Wx,    p_t,  1024, 256, 256, b_cat, nullptr);
    sgemm64<<<dim3(8, 4),  256>>>(p_g,      W1_0,  p_A1g, 256, 512, 256, nullptr, nullptr);
    sgemm64<<<dim3(8, 16), 256>>>(p_t,      W1_0,  p_A1t,1024, 512, 256, b1,    nullptr);
    sgemm64<<<dim3(8, 4),  256>>>(p_g,      W1_1,  p_A2g, 256, 512, 256, nullptr, nullptr);
    sgemm64<<<dim3(8, 16), 256>>>(p_t,      W1_1,  p_A2t,1024, 512, 256, p_bu2, nullptr);
    sgemm64<<<dim3(4, 4),  256>>>(p_g,      W_out, p_Og,  256, 256, 256, nullptr, codebook);
    sgemm64<<<dim3(4, 16), 256>>>(p_t,      W_out, p_Ot, 1024, 256, 256, p_bo,  xhat);
    sgemm64<<<dim3(8, 8),  256>>>(W2_0,     W1_1,  p_M12, 512, 512, 256, nullptr, nullptr);
    sgemm64<<<dim3(4, 8),  256>>>(W2_0,     W_out, p_M1o, 512, 256, 256, nullptr, nullptr);
    sgemm64<<<dim3(4, 8),  256>>>(W2_1,     W_out, p_M2o, 512, 256, 256, nullptr, nullptr);

    // main distance pass
    const int smem_bytes = DIST_SMEM_FLOATS * (int)sizeof(float);  // 103424
    cudaFuncSetAttribute(dist_kernel, cudaFuncAttributeMaxDynamicSharedMemorySize, smem_bytes);
    dist_kernel<<<Bb * Ff, 256, smem_bytes>>>(x);

    argmin_kernel<<<Bb, 256>>>();
    final_kernel<<<Bb, 512>>>(out);
    codes_kernel<<<1, 384>>>(codes, out);
}